// round 12
// baseline (speedup 1.0000x reference)
#include <cuda_runtime.h>
#include <cuda_bf16.h>
#include <cstdint>

#define LL 2048
#define BB 64
#define KK 4
#define CC 128
#define NITEMS 32768
#define NPAIRS (NITEMS / 2)                       // 16384
#define NPERM 24
#define WARPS_PER_BLOCK 4
#define NBLOCKS 1024
#define TOTAL_WARPS (NBLOCKS * WARPS_PER_BLOCK)   // 4096
#define PAIRS_PER_WARP (NPAIRS / TOTAL_WARPS)     // 4

__device__ double g_acc;
__device__ unsigned int g_count;

// permutations of {0,1,2,3}, one byte per position (little-endian)
__constant__ unsigned int c_perms[NPERM] = {
    0x03020100u, 0x02030100u, 0x03010200u, 0x01030200u, 0x02010300u, 0x01020300u,
    0x03020001u, 0x02030001u, 0x03000201u, 0x00030201u, 0x02000301u, 0x00020301u,
    0x03010002u, 0x01030002u, 0x03000102u, 0x00030102u, 0x01000302u, 0x00010302u,
    0x02010003u, 0x01020003u, 0x02000103u, 0x00020103u, 0x01000203u, 0x00010203u
};

__device__ __forceinline__ float exps4(float4 v) {
    return __expf(v.x) + __expf(v.y) + __expf(v.z) + __expf(v.w);
}

__device__ __forceinline__ void cp16(unsigned int dst, const float* src) {
    asm volatile("cp.async.ca.shared.global [%0], [%1], 16;"
                 :: "r"(dst), "l"(src));
}

struct Scal {
    float tw0, twt, awt, ot, oa, ps;
    int cwt, valid;
};

__global__ __launch_bounds__(128, 7) void detpp_fused_kernel(
    const float* __restrict__ in_time,     // (L, B)
    const float* __restrict__ in_amount,   // (L, B)
    const int*   __restrict__ in_mcc,      // (L, B)
    const float* __restrict__ out_time,    // (L, B, K)
    const float* __restrict__ out_amount,  // (L, B, K)
    const float* __restrict__ out_logits,  // (L, B, K, C)
    const float* __restrict__ presence,    // (L, B, K)
    const int*   __restrict__ indices,     // (I, B)
    const int*   __restrict__ subset_lengths, // (B,)
    float*       __restrict__ out)
{
    // 2 stages x 4 warps x 8 chunks x 32 lanes x 16B = 32768 B exactly.
    // [j][lane] layout -> float4-per-lane access is conflict-free.
    __shared__ float4 sbuf[2][WARPS_PER_BLOCK][8][32];

    int tid  = threadIdx.x;
    int wid  = tid >> 5;
    int lane = tid & 31;
    int hl   = lane & 15;
    int half = lane >> 4;          // which item of the pair this lane serves
    int k = (lane >> 2) & 3;
    int t = lane & 3;

    int gwarp = blockIdx.x * WARPS_PER_BLOCK + wid;

    // loop-invariant permutation words (registers, not smem)
    unsigned int pm1 = c_perms[hl];
    unsigned int pm2 = c_perms[(hl < 8) ? (hl + 16) : hl];

    int c0 = half * CC + hl * 4;
    int c2 = (2 + half) * CC + hl * 4;

    // issue 8 x 16B cp.async for one pair's logit fragments into stage s
    auto issue_pair = [&](int pair, int s) {
        int it0 = pair * 2, it1 = it0 + 1;
        int b0 = it0 & (BB - 1), i0 = it0 >> 6;
        int b1 = it1 & (BB - 1), i1 = it1 >> 6;
        int idx0 = indices[i0 * BB + b0];
        int idx1 = indices[i1 * BB + b1];
        const float* lp0 = out_logits + (size_t)(idx0 * BB + b0) * (KK * CC);
        const float* lp1 = out_logits + (size_t)(idx1 * BB + b1) * (KK * CC);
        unsigned int base = (unsigned int)__cvta_generic_to_shared(&sbuf[s][wid][0][lane]);
        cp16(base + 0 * 512, lp0 + c0);
        cp16(base + 1 * 512, lp0 + c0 + 64);
        cp16(base + 2 * 512, lp0 + c2);
        cp16(base + 3 * 512, lp0 + c2 + 64);
        cp16(base + 4 * 512, lp1 + c0);
        cp16(base + 5 * 512, lp1 + c0 + 64);
        cp16(base + 6 * 512, lp1 + c2);
        cp16(base + 7 * 512, lp1 + c2 + 64);
        asm volatile("cp.async.commit_group;" ::: "memory");
    };

    // small scalar gathers for this lane's item of the pair (prefetched 1 ahead)
    auto load_scal = [&](int pair) -> Scal {
        Scal S;
        int it0 = pair * 2, it1 = it0 + 1;
        int bX, iX;
        if (half) { bX = it1 & (BB - 1); iX = it1 >> 6; }
        else      { bX = it0 & (BB - 1); iX = it0 >> 6; }
        S.valid = iX < subset_lengths[bX];
        int idxX = indices[iX * BB + bX];
        int rowX = idxX * BB + bX;
        S.tw0 = in_time[rowX];
        int r = idxX + t + 1;
        if (r >= LL) r -= LL;              // roll wrap (unreachable for valid items)
        int rr = r * BB + bX;
        S.twt = in_time[rr];
        S.awt = in_amount[rr];
        S.cwt = in_mcc[rr];
        int ob = rowX * KK + k;
        S.ot = out_time[ob];
        S.oa = out_amount[ob];
        S.ps = presence[ob];
        return S;
    };

    // ---- prologue ----
    issue_pair(gwarp, 0);
    Scal cur = load_scal(gwarp);

    float warp_tot = 0.f;

    #pragma unroll
    for (int itr = 0; itr < PAIRS_PER_WARP; itr++) {
        int s = itr & 1;
        asm volatile("cp.async.wait_group 0;" ::: "memory");
        __syncwarp();

        // sel from SMEM (no dependent LDG!): item=half, row=k, col=cwt
        int cwt = cur.cwt;
        int jsel = half * 4 + ((k >> 1) << 1) + (cwt >= 64 ? 1 : 0);
        int lsel = (k & 1) * 16 + ((cwt & 63) >> 2);
        float sel = reinterpret_cast<const float*>(&sbuf[s][wid][jsel][lsel])[cwt & 3];

        // prefetch next pair while computing this one
        Scal nxt;
        if (itr + 1 < PAIRS_PER_WARP) {
            int np = gwarp + (itr + 1) * TOTAL_WARPS;
            issue_pair(np, s ^ 1);
            nxt = load_scal(np);
        }

        // ---- exp sums from smem (conflict-free float4 loads) ----
        const float4* st = &sbuf[s][wid][0][lane];
        float s01 = exps4(st[0 * 32]) + exps4(st[1 * 32]);
        float s23 = exps4(st[2 * 32]) + exps4(st[3 * 32]);
        float u01 = exps4(st[4 * 32]) + exps4(st[5 * 32]);
        float u23 = exps4(st[6 * 32]) + exps4(st[7 * 32]);

        // ---- 4 interleaved half-warp butterflies (xor 1,2,4,8) ----
        #pragma unroll
        for (int o = 8; o; o >>= 1) {
            s01 += __shfl_xor_sync(0xffffffffu, s01, o);
            s23 += __shfl_xor_sync(0xffffffffu, s23, o);
            u01 += __shfl_xor_sync(0xffffffffu, u01, o);
            u23 += __shfl_xor_sync(0xffffffffu, u23, o);
        }
        float hs01 = __shfl_xor_sync(0xffffffffu, s01, 16);
        float hs23 = __shfl_xor_sync(0xffffffffu, s23, 16);
        float hu01 = __shfl_xor_sync(0xffffffffu, u01, 16);
        float hu23 = __shfl_xor_sync(0xffffffffu, u23, 16);

        float r0s = half ? hu01 : s01;
        float r1s = half ? u01  : hs01;
        float r2s = half ? hu23 : s23;
        float r3s = half ? u23  : hs23;
        float sk = (k == 0) ? r0s : (k == 1) ? r1s : (k == 2) ? r2s : r3s;

        // ---- cost entry (16 per item, one per lane) ----
        float cost = __logf(sk) - sel
                   + fabsf(cur.ot - (cur.twt - cur.tw0))
                   + fabsf(cur.oa - cur.awt)
                   - cur.ps;
        float soft = 0.f;
        if (t == 0) {
            soft = (cur.ps > 0.f) ? cur.ps + __logf(1.f + __expf(-cur.ps))
                                  : __logf(1.f + __expf(cur.ps));
        }

        // ---- exact assignment: 24 perms per item, 2 perms per lane ----
        int base = lane & 16;
        float pc1 = 0.f, pc2 = 0.f;
        #pragma unroll
        for (int kk = 0; kk < KK; kk++) {
            int sA = base + (kk << 2) + ((pm1 >> (8 * kk)) & 3);
            int sB = base + (kk << 2) + ((pm2 >> (8 * kk)) & 3);
            pc1 += __shfl_sync(0xffffffffu, cost, sA);
            pc2 += __shfl_sync(0xffffffffu, cost, sB);
        }
        float pc = fminf(pc1, (hl < 8) ? pc2 : 3.4e38f);
        #pragma unroll
        for (int o = 8; o; o >>= 1)
            pc = fminf(pc, __shfl_xor_sync(0xffffffffu, pc, o));

        // softplus sum within half (t==0 lanes are {0,4,8,12}+base)
        soft += __shfl_xor_sync(0xffffffffu, soft, 4);
        soft += __shfl_xor_sync(0xffffffffu, soft, 8);

        float half_tot = cur.valid ? (pc + soft) : 0.f;
        half_tot += __shfl_xor_sync(0xffffffffu, half_tot, 16);
        warp_tot += half_tot;              // lane 0's value is the correct one

        cur = nxt;
    }

    // ---- block reduction: overlay accumulator on the (now dead) smem buffer ----
    __syncthreads();
    double* s_acc = reinterpret_cast<double*>(&sbuf[0][0][0][0]);
    int* s_islast = reinterpret_cast<int*>(s_acc + 1);
    if (tid == 0) *s_acc = 0.0;
    __syncthreads();
    if (lane == 0)
        atomicAdd(s_acc, (double)warp_tot);
    __syncthreads();

    if (tid == 0) {
        atomicAdd(&g_acc, *s_acc);
        __threadfence();
        unsigned int done = atomicAdd(&g_count, 1u);
        *s_islast = (done == (unsigned)(NBLOCKS - 1));
    }
    __syncthreads();

    if (*s_islast && tid == 0) {
        double acc = g_acc;
        int vv = 0;
        #pragma unroll
        for (int bb = 0; bb < BB; bb++) vv += subset_lengths[bb];
        out[0] = (float)(acc / (double)vv);
        g_acc = 0.0;                 // reset for next graph replay
        g_count = 0u;
    }
}

extern "C" void kernel_launch(void* const* d_in, const int* in_sizes, int n_in,
                              void* d_out, int out_size)
{
    const float* in_time        = (const float*)d_in[0];
    const float* in_amount      = (const float*)d_in[1];
    const int*   in_mcc         = (const int*)  d_in[2];
    const float* out_time       = (const float*)d_in[3];
    const float* out_amount     = (const float*)d_in[4];
    const float* out_logits     = (const float*)d_in[5];
    const float* presence       = (const float*)d_in[6];
    // d_in[7] = lengths (unused; subset_lengths already encodes validity)
    const int*   indices        = (const int*)  d_in[8];
    const int*   subset_lengths = (const int*)  d_in[9];
    float* out = (float*)d_out;

    detpp_fused_kernel<<<NBLOCKS, 128>>>(
        in_time, in_amount, in_mcc, out_time, out_amount,
        out_logits, presence, indices, subset_lengths, out);
}

// round 14
// speedup vs baseline: 1.2217x; 1.2217x over previous
#include <cuda_runtime.h>
#include <cuda_bf16.h>
#include <cstdint>

#define LL 2048
#define BB 64
#define KK 4
#define CC 128
#define NITEMS 32768
#define NPAIRS (NITEMS / 2)                       // 16384
#define NPERM 24
#define WARPS_PER_BLOCK 8
#define NBLOCKS 1024                              // one wave (<= 7*148)
#define TOTAL_WARPS (NBLOCKS * WARPS_PER_BLOCK)   // 8192
#define PAIRS_PER_WARP (NPAIRS / TOTAL_WARPS)     // 2

__device__ double g_acc;
__device__ unsigned int g_count;

// permutations of {0,1,2,3}, one byte per position (little-endian)
__constant__ unsigned int c_perms[NPERM] = {
    0x03020100u, 0x02030100u, 0x03010200u, 0x01030200u, 0x02010300u, 0x01020300u,
    0x03020001u, 0x02030001u, 0x03000201u, 0x00030201u, 0x02000301u, 0x00020301u,
    0x03010002u, 0x01030002u, 0x03000102u, 0x00030102u, 0x01000302u, 0x00010302u,
    0x02010003u, 0x01020003u, 0x02000103u, 0x00020103u, 0x01000203u, 0x00010203u
};

__device__ __forceinline__ float exps4(float4 v) {
    return __expf(v.x) + __expf(v.y) + __expf(v.z) + __expf(v.w);
}

__global__ __launch_bounds__(256, 7) void detpp_fused_kernel(
    const float* __restrict__ in_time,     // (L, B)
    const float* __restrict__ in_amount,   // (L, B)
    const int*   __restrict__ in_mcc,      // (L, B)
    const float* __restrict__ out_time,    // (L, B, K)
    const float* __restrict__ out_amount,  // (L, B, K)
    const float* __restrict__ out_logits,  // (L, B, K, C)
    const float* __restrict__ presence,    // (L, B, K)
    const int*   __restrict__ indices,     // (I, B)
    const int*   __restrict__ subset_lengths, // (B,)
    float*       __restrict__ out)
{
    // phase-A -> phase-B handoff buffers
    __shared__ float s_cost[WARPS_PER_BLOCK][PAIRS_PER_WARP][2][16];  // 4 KB
    __shared__ float s_soft[WARPS_PER_BLOCK][PAIRS_PER_WARP][2][4];   // 1 KB
    __shared__ double s_acc;
    __shared__ int s_islast;

    int tid  = threadIdx.x;
    int wid  = tid >> 5;
    int lane = tid & 31;
    int hl   = lane & 15;
    int half = lane >> 4;          // which item of the pair this lane serves
    int k = (lane >> 2) & 3;
    int t = lane & 3;

    if (tid == 0) s_acc = 0.0;
    __syncthreads();

    int gwarp = blockIdx.x * WARPS_PER_BLOCK + wid;

    int c0 = half * CC + hl * 4;
    int c2 = (2 + half) * CC + hl * 4;

    int validbits = 0;

    // ================= PHASE A: memory loop (no perm work) =================
    #pragma unroll
    for (int itr = 0; itr < PAIRS_PER_WARP; itr++) {
        int pair = gwarp + itr * TOTAL_WARPS;
        int it0 = pair * 2, it1 = it0 + 1;
        int b0 = it0 & (BB - 1), i0 = it0 >> 6;
        int b1 = it1 & (BB - 1), i1 = it1 >> 6;

        int idx0 = indices[i0 * BB + b0];
        int idx1 = indices[i1 * BB + b1];
        int row0 = idx0 * BB + b0;
        int row1 = idx1 * BB + b1;
        const float* lp0 = out_logits + (size_t)row0 * (KK * CC);
        const float* lp1 = out_logits + (size_t)row1 * (KK * CC);

        // ---- logit loads: 2 rows per instr, 256B contiguous per half ----
        float4 a01a = *reinterpret_cast<const float4*>(lp0 + c0);
        float4 a01b = *reinterpret_cast<const float4*>(lp0 + c0 + 64);
        float4 a23a = *reinterpret_cast<const float4*>(lp0 + c2);
        float4 a23b = *reinterpret_cast<const float4*>(lp0 + c2 + 64);
        float4 b01a = *reinterpret_cast<const float4*>(lp1 + c0);
        float4 b01b = *reinterpret_cast<const float4*>(lp1 + c0 + 64);
        float4 b23a = *reinterpret_cast<const float4*>(lp1 + c2);
        float4 b23b = *reinterpret_cast<const float4*>(lp1 + c2 + 64);

        // ---- scalar gathers (half-warp per item, all 32 lanes active) ----
        int idxX = half ? idx1 : idx0;
        int bX   = half ? b1   : b0;
        int rowX = half ? row1 : row0;
        const float* lpX = half ? lp1 : lp0;
        int vX = half ? (i1 < subset_lengths[b1]) : (i0 < subset_lengths[b0]);
        validbits |= vX << itr;

        float tw0 = in_time[rowX];
        int r = idxX + t + 1;
        if (r >= LL) r -= LL;             // roll wrap (unreachable for valid items)
        int rr = r * BB + bX;
        float twt = in_time[rr];
        float awt = in_amount[rr];
        int   cwt = in_mcc[rr];
        int obase = rowX * KK + k;
        float ot = out_time[obase];
        float oa = out_amount[obase];
        float ps = presence[obase];
        float sel = lpX[k * CC + cwt];    // L1-hot (row just streamed)

        // ---- exp sums (no max shift: logits ~ N(0,1), fp32-safe) ----
        float s01 = exps4(a01a) + exps4(a01b);
        float s23 = exps4(a23a) + exps4(a23b);
        float u01 = exps4(b01a) + exps4(b01b);
        float u23 = exps4(b23a) + exps4(b23b);

        // ---- 4 interleaved half-warp butterflies (xor 1,2,4,8) ----
        #pragma unroll
        for (int o = 8; o; o >>= 1) {
            s01 += __shfl_xor_sync(0xffffffffu, s01, o);
            s23 += __shfl_xor_sync(0xffffffffu, s23, o);
            u01 += __shfl_xor_sync(0xffffffffu, u01, o);
            u23 += __shfl_xor_sync(0xffffffffu, u23, o);
        }
        float hs01 = __shfl_xor_sync(0xffffffffu, s01, 16);
        float hs23 = __shfl_xor_sync(0xffffffffu, s23, 16);
        float hu01 = __shfl_xor_sync(0xffffffffu, u01, 16);
        float hu23 = __shfl_xor_sync(0xffffffffu, u23, 16);

        float r0s = half ? hu01 : s01;
        float r1s = half ? u01  : hs01;
        float r2s = half ? hu23 : s23;
        float r3s = half ? u23  : hs23;
        float sk = (k == 0) ? r0s : (k == 1) ? r1s : (k == 2) ? r2s : r3s;

        // ---- cost entry -> SMEM (perm deferred to phase B) ----
        float cost = __logf(sk) - sel
                   + fabsf(ot - (twt - tw0))
                   + fabsf(oa - awt)
                   - ps;
        s_cost[wid][itr][half][hl] = cost;
        if (t == 0) {
            s_soft[wid][itr][half][k] =
                (ps > 0.f) ? ps + __logf(1.f + __expf(-ps))
                           : __logf(1.f + __expf(ps));
        }
    }

    __syncwarp();

    // ================= PHASE B: assignment tail (SMEM-fed) =================
    unsigned int pm1 = c_perms[hl];
    unsigned int pm2 = c_perms[(hl < 8) ? (hl + 16) : hl];
    int base = lane & 16;

    float warp_tot = 0.f;

    #pragma unroll
    for (int itr = 0; itr < PAIRS_PER_WARP; itr++) {
        float cost = s_cost[wid][itr][half][hl];

        // independent perm gathers + tree add (short chain)
        float g0 = __shfl_sync(0xffffffffu, cost, base + 0  + ( pm1        & 3));
        float g1 = __shfl_sync(0xffffffffu, cost, base + 4  + ((pm1 >> 8)  & 3));
        float g2 = __shfl_sync(0xffffffffu, cost, base + 8  + ((pm1 >> 16) & 3));
        float g3 = __shfl_sync(0xffffffffu, cost, base + 12 + ((pm1 >> 24) & 3));
        float h0 = __shfl_sync(0xffffffffu, cost, base + 0  + ( pm2        & 3));
        float h1 = __shfl_sync(0xffffffffu, cost, base + 4  + ((pm2 >> 8)  & 3));
        float h2 = __shfl_sync(0xffffffffu, cost, base + 8  + ((pm2 >> 16) & 3));
        float h3 = __shfl_sync(0xffffffffu, cost, base + 12 + ((pm2 >> 24) & 3));
        float pc1 = (g0 + g1) + (g2 + g3);
        float pc2 = (h0 + h1) + (h2 + h3);

        float pc = fminf(pc1, (hl < 8) ? pc2 : 3.4e38f);
        #pragma unroll
        for (int o = 8; o; o >>= 1)
            pc = fminf(pc, __shfl_xor_sync(0xffffffffu, pc, o));

        // softplus total: broadcast reads (bank-conflict-free, N=1)
        const float* sp = s_soft[wid][itr][half];
        float soft = (sp[0] + sp[1]) + (sp[2] + sp[3]);

        float half_tot = ((validbits >> itr) & 1) ? (pc + soft) : 0.f;
        half_tot += __shfl_xor_sync(0xffffffffu, half_tot, 16);
        warp_tot += half_tot;              // lane 0's value is the correct one
    }

    if (lane == 0)
        atomicAdd(&s_acc, (double)warp_tot);

    __syncthreads();

    // ---- grid-level reduction: last block finalizes ----
    if (tid == 0) {
        atomicAdd(&g_acc, s_acc);
        __threadfence();
        unsigned int done = atomicAdd(&g_count, 1u);
        s_islast = (done == (unsigned)(NBLOCKS - 1));
    }
    __syncthreads();

    if (s_islast && tid == 0) {
        double acc = g_acc;
        int vv = 0;
        #pragma unroll
        for (int bb = 0; bb < BB; bb++) vv += subset_lengths[bb];
        out[0] = (float)(acc / (double)vv);
        g_acc = 0.0;                 // reset for next graph replay
        g_count = 0u;
    }
}

extern "C" void kernel_launch(void* const* d_in, const int* in_sizes, int n_in,
                              void* d_out, int out_size)
{
    const float* in_time        = (const float*)d_in[0];
    const float* in_amount      = (const float*)d_in[1];
    const int*   in_mcc         = (const int*)  d_in[2];
    const float* out_time       = (const float*)d_in[3];
    const float* out_amount     = (const float*)d_in[4];
    const float* out_logits     = (const float*)d_in[5];
    const float* presence       = (const float*)d_in[6];
    // d_in[7] = lengths (unused; subset_lengths already encodes validity)
    const int*   indices        = (const int*)  d_in[8];
    const int*   subset_lengths = (const int*)  d_in[9];
    float* out = (float*)d_out;

    detpp_fused_kernel<<<NBLOCKS, 256>>>(
        in_time, in_amount, in_mcc, out_time, out_amount,
        out_logits, presence, indices, subset_lengths, out);
}